// round 8
// baseline (speedup 1.0000x reference)
#include <cuda_runtime.h>

// Problem constants
#define DIMC   192
#define NHEAD  6
#define HD     32
#define NT     49          // tokens per window
#define NWIN   64          // windows per image (mask dim)
#define BWIN   4096        // total windows
#define NTHR   256

#define STR    196         // padded row stride (floats), multiple of 4 for LDS.128

// Shared memory layout (floats)
#define XS_OFF 0                       // 49*196  (x, later reused as ctx)
#define QS_OFF (XS_OFF + NT*STR)
#define KS_OFF (QS_OFF + NT*STR)
#define VS_OFF (KS_OFF + NT*STR)
#define WT_OFF (VS_OFF + NT*STR)       // 64*196  weight tile, o-major
#define LG_OFF (WT_OFF + 64*STR)       // 2401 (padded to 2404)
#define RI_OFF (LG_OFF + 2404)
#define SMEM_FLOATS (RI_OFF + NT*NT)
#define SMEM_BYTES  (SMEM_FLOATS * 4)  // 223060 B

__device__ __forceinline__ float dot4(float4 a, float4 b, float acc) {
    acc = fmaf(a.x, b.x, acc);
    acc = fmaf(a.y, b.y, acc);
    acc = fmaf(a.z, b.z, acc);
    acc = fmaf(a.w, b.w, acc);
    return acc;
}

__global__ __launch_bounds__(NTHR, 1)
void win_attn_fused(const float* __restrict__ x,
                    const float* __restrict__ mask,
                    const float* __restrict__ qkv_w,
                    const float* __restrict__ qkv_b,
                    const float* __restrict__ proj_w,
                    const float* __restrict__ proj_b,
                    const float* __restrict__ rpb,
                    const int*   __restrict__ rel_idx,
                    float* __restrict__ out,       // [4096,49,192]
                    float* __restrict__ attn_out)  // [4096,6,49,49]
{
    extern __shared__ float sm[];
    float* xs = sm + XS_OFF;   // x, then ctx
    float* qs = sm + QS_OFF;
    float* ks = sm + KS_OFF;
    float* vs = sm + VS_OFF;
    float* wt = sm + WT_OFF;   // o-major: wt[o*STR + kk]
    float* lg = sm + LG_OFF;
    int*   ri = (int*)(sm + RI_OFF);

    const int b = blockIdx.x;
    const int t = threadIdx.x;

    // ---- load x[b] (float4, padded rows) + rel_idx ----
    const float* xb = x + (size_t)b * NT * DIMC;
    for (int idx = t; idx < NT * 48; idx += NTHR) {
        int r = idx / 48, c4 = idx - r * 48;
        *(float4*)&xs[r * STR + c4 * 4] = *(const float4*)&xb[r * DIMC + c4 * 4];
    }
    for (int idx = t; idx < NT * NT; idx += NTHR) ri[idx] = rel_idx[idx];

    const int oq = t & 15;    // output column sub-lane within 64-tile
    const int rg = t >> 4;    // row group 0..15: rows rg + 16*i

    int roff[4];
    #pragma unroll
    for (int i = 0; i < 4; ++i) {
        int r = rg + 16 * i;
        roff[i] = (r < NT ? r : NT - 1) * STR;   // clamp (stores are guarded)
    }

    // ==================== QKV projection ====================
    for (int tile = 0; tile < 9; ++tile) {
        __syncthreads();  // protect wt from previous tile's readers
        // fill wt o-major (float4 over k)
        for (int idx = t; idx < 64 * 48; idx += NTHR) {
            int o = idx / 48, k4 = idx - o * 48;
            *(float4*)&wt[o * STR + k4 * 4] =
                *(const float4*)&qkv_w[(tile * 64 + o) * DIMC + k4 * 4];
        }
        __syncthreads();

        float acc[4][4];
        #pragma unroll
        for (int i = 0; i < 4; ++i)
            #pragma unroll
            for (int w = 0; w < 4; ++w) acc[i][w] = 0.f;

        for (int kk = 0; kk < DIMC; kk += 4) {
            float4 wv[4];
            #pragma unroll
            for (int w = 0; w < 4; ++w)
                wv[w] = *(const float4*)&wt[(oq + 16 * w) * STR + kk];
            #pragma unroll
            for (int i = 0; i < 4; ++i) {
                float4 xv = *(const float4*)&xs[roff[i] + kk];
                #pragma unroll
                for (int w = 0; w < 4; ++w) acc[i][w] = dot4(xv, wv[w], acc[i][w]);
            }
        }

        int s = tile / 3;
        int cbase = (tile - s * 3) * 64;
        float* dst = (s == 0) ? qs : (s == 1 ? ks : vs);
        #pragma unroll
        for (int i = 0; i < 4; ++i) {
            int r = rg + 16 * i;
            if (r < NT) {
                #pragma unroll
                for (int w = 0; w < 4; ++w) {
                    int c  = cbase + oq + 16 * w;
                    int og = tile * 64 + oq + 16 * w;
                    dst[r * STR + c] = acc[i][w] + qkv_b[og];
                }
            }
        }
    }

    // ==================== attention per head ====================
    const float scale = 0.17677669529663687f;  // 32^-0.5
    const float* mrow = mask + (size_t)(b & (NWIN - 1)) * NT * NT;
    const int warp = t >> 5, lane = t & 31;
    const int ti = t >> 4, tj = t & 15;     // 16x16 logit thread grid
    const int av_i = t >> 2, av_d8 = t & 3; // AV: 64 rows x 4 d-groups

    for (int h = 0; h < NHEAD; ++h) {
        __syncthreads();  // qkv ready (h=0) / prev AV done reading lg (h>0)

        // ---- logits = scale*q.k + bias + mask (4x4 register tile, float4) ----
        {
            int ioff[4], joff[4];
            #pragma unroll
            for (int a = 0; a < 4; ++a) {
                int ia = ti + 16 * a;
                ioff[a] = (ia < NT ? ia : NT - 1) * STR + h * HD;
                int jb = tj + 16 * a;
                joff[a] = (jb < NT ? jb : NT - 1) * STR + h * HD;
            }
            float acc[4][4];
            #pragma unroll
            for (int a = 0; a < 4; ++a)
                #pragma unroll
                for (int c = 0; c < 4; ++c) acc[a][c] = 0.f;

            #pragma unroll
            for (int d = 0; d < HD; d += 4) {
                float4 q4[4], k4[4];
                #pragma unroll
                for (int a = 0; a < 4; ++a) q4[a] = *(const float4*)&qs[ioff[a] + d];
                #pragma unroll
                for (int c = 0; c < 4; ++c) k4[c] = *(const float4*)&ks[joff[c] + d];
                #pragma unroll
                for (int a = 0; a < 4; ++a)
                    #pragma unroll
                    for (int c = 0; c < 4; ++c) acc[a][c] = dot4(q4[a], k4[c], acc[a][c]);
            }

            #pragma unroll
            for (int a = 0; a < 4; ++a) {
                int i = ti + 16 * a;
                if (i < NT) {
                    #pragma unroll
                    for (int c = 0; c < 4; ++c) {
                        int j = tj + 16 * c;
                        if (j < NT) {
                            int idx = i * NT + j;
                            lg[idx] = acc[a][c] * scale
                                    + rpb[ri[idx] * NHEAD + h] + mrow[idx];
                        }
                    }
                }
            }
        }
        __syncthreads();

        // ---- softmax: one warp per row ----
        for (int i = warp; i < NT; i += 8) {
            float l1 = lg[i * NT + lane];
            bool  v2 = (lane + 32) < NT;
            float l2 = v2 ? lg[i * NT + lane + 32] : -1e30f;
            float m = fmaxf(l1, l2);
            #pragma unroll
            for (int o = 16; o; o >>= 1) m = fmaxf(m, __shfl_xor_sync(0xffffffffu, m, o));
            float e1 = __expf(l1 - m);
            float e2 = v2 ? __expf(l2 - m) : 0.f;
            float s2 = e1 + e2;
            #pragma unroll
            for (int o = 16; o; o >>= 1) s2 += __shfl_xor_sync(0xffffffffu, s2, o);
            float inv = 1.f / s2;
            float p1 = e1 * inv, p2 = e2 * inv;
            lg[i * NT + lane] = p1;
            if (v2) lg[i * NT + lane + 32] = p2;
            float* arow = attn_out + (((size_t)b * NHEAD + h) * NT + i) * NT;
            arow[lane] = p1;
            if (v2) arow[lane + 32] = p2;
        }
        __syncthreads();

        // ---- ctx[:, h*32+d] = attn @ v (float4 v loads, broadcast p) ----
        {
            int ii = (av_i < NT ? av_i : NT - 1);
            const float* pr = lg + ii * NT;
            const float* vb = vs + h * HD + av_d8 * 8;
            float4 a0 = make_float4(0.f, 0.f, 0.f, 0.f);
            float4 a1 = make_float4(0.f, 0.f, 0.f, 0.f);
            #pragma unroll 7
            for (int j = 0; j < NT; ++j) {
                float  p  = pr[j];
                float4 va = *(const float4*)&vb[j * STR];
                float4 vc = *(const float4*)&vb[j * STR + 4];
                a0.x = fmaf(p, va.x, a0.x); a0.y = fmaf(p, va.y, a0.y);
                a0.z = fmaf(p, va.z, a0.z); a0.w = fmaf(p, va.w, a0.w);
                a1.x = fmaf(p, vc.x, a1.x); a1.y = fmaf(p, vc.y, a1.y);
                a1.z = fmaf(p, vc.z, a1.z); a1.w = fmaf(p, vc.w, a1.w);
            }
            if (av_i < NT) {
                *(float4*)&xs[av_i * STR + h * HD + av_d8 * 8]     = a0;
                *(float4*)&xs[av_i * STR + h * HD + av_d8 * 8 + 4] = a1;
            }
        }
    }

    // ==================== output projection ====================
    for (int tile = 0; tile < 3; ++tile) {
        __syncthreads();  // AV done (tile 0) / prev tile's readers done
        for (int idx = t; idx < 64 * 48; idx += NTHR) {
            int o = idx / 48, k4 = idx - o * 48;
            *(float4*)&wt[o * STR + k4 * 4] =
                *(const float4*)&proj_w[(tile * 64 + o) * DIMC + k4 * 4];
        }
        __syncthreads();

        float acc[4][4];
        #pragma unroll
        for (int i = 0; i < 4; ++i)
            #pragma unroll
            for (int w = 0; w < 4; ++w) acc[i][w] = 0.f;

        for (int kk = 0; kk < DIMC; kk += 4) {
            float4 wv[4];
            #pragma unroll
            for (int w = 0; w < 4; ++w)
                wv[w] = *(const float4*)&wt[(oq + 16 * w) * STR + kk];
            #pragma unroll
            for (int i = 0; i < 4; ++i) {
                float4 xv = *(const float4*)&xs[roff[i] + kk];
                #pragma unroll
                for (int w = 0; w < 4; ++w) acc[i][w] = dot4(xv, wv[w], acc[i][w]);
            }
        }

        #pragma unroll
        for (int i = 0; i < 4; ++i) {
            int r = rg + 16 * i;
            if (r < NT) {
                #pragma unroll
                for (int w = 0; w < 4; ++w) {
                    int c = tile * 64 + oq + 16 * w;
                    out[((size_t)b * NT + r) * DIMC + c] = acc[i][w] + proj_b[c];
                }
            }
        }
    }
}

extern "C" void kernel_launch(void* const* d_in, const int* in_sizes, int n_in,
                              void* d_out, int out_size)
{
    const float* x      = (const float*)d_in[0];
    const float* mask   = (const float*)d_in[1];
    const float* qkv_w  = (const float*)d_in[2];
    const float* qkv_b  = (const float*)d_in[3];
    const float* proj_w = (const float*)d_in[4];
    const float* proj_b = (const float*)d_in[5];
    const float* rpb    = (const float*)d_in[6];
    const int*   relidx = (const int*)  d_in[7];

    float* out      = (float*)d_out;                         // [4096,49,192]
    float* attn_out = out + (size_t)BWIN * NT * DIMC;        // [4096,6,49,49]

    cudaFuncSetAttribute(win_attn_fused,
                         cudaFuncAttributeMaxDynamicSharedMemorySize, SMEM_BYTES);

    win_attn_fused<<<BWIN, NTHR, SMEM_BYTES>>>(
        x, mask, qkv_w, qkv_b, proj_w, proj_b, rpb, relidx, out, attn_out);
}

// round 9
// speedup vs baseline: 1.0017x; 1.0017x over previous
#include <cuda_runtime.h>

// Problem constants
#define DIMC   192
#define NHEAD  6
#define HD     32
#define NT     49          // tokens per window
#define NWIN   64          // windows per image (mask dim)
#define BWIN   4096        // total windows
#define NTHR   256

#define STR    196         // padded row stride (floats), multiple of 4 for LDS.128

// Shared memory layout (floats)
#define XS_OFF 0                       // 49*196  (x, later reused as ctx)
#define QS_OFF (XS_OFF + NT*STR)
#define KS_OFF (QS_OFF + NT*STR)
#define VS_OFF (KS_OFF + NT*STR)
#define WT_OFF (VS_OFF + NT*STR)       // 64*196  weight tile, o-major
#define LG_OFF (WT_OFF + 64*STR)       // 2401 (padded to 2404)
#define RI_OFF (LG_OFF + 2404)
#define SMEM_FLOATS (RI_OFF + NT*NT)
#define SMEM_BYTES  (SMEM_FLOATS * 4)  // 223060 B

__device__ __forceinline__ float dot4(float4 a, float4 b, float acc) {
    acc = fmaf(a.x, b.x, acc);
    acc = fmaf(a.y, b.y, acc);
    acc = fmaf(a.z, b.z, acc);
    acc = fmaf(a.w, b.w, acc);
    return acc;
}

__global__ __launch_bounds__(NTHR, 1)
void win_attn_fused(const float* __restrict__ x,
                    const float* __restrict__ mask,
                    const float* __restrict__ qkv_w,
                    const float* __restrict__ qkv_b,
                    const float* __restrict__ proj_w,
                    const float* __restrict__ proj_b,
                    const float* __restrict__ rpb,
                    const int*   __restrict__ rel_idx,
                    float* __restrict__ out,       // [4096,49,192]
                    float* __restrict__ attn_out)  // [4096,6,49,49]
{
    extern __shared__ float sm[];
    float* xs = sm + XS_OFF;   // x, then ctx
    float* qs = sm + QS_OFF;
    float* ks = sm + KS_OFF;
    float* vs = sm + VS_OFF;
    float* wt = sm + WT_OFF;   // o-major: wt[o*STR + kk]
    float* lg = sm + LG_OFF;
    int*   ri = (int*)(sm + RI_OFF);

    const int b = blockIdx.x;
    const int t = threadIdx.x;

    // ---- load x[b] (float4, padded rows) + rel_idx ----
    const float* xb = x + (size_t)b * NT * DIMC;
    for (int idx = t; idx < NT * 48; idx += NTHR) {
        int r = idx / 48, c4 = idx - r * 48;
        *(float4*)&xs[r * STR + c4 * 4] = *(const float4*)&xb[r * DIMC + c4 * 4];
    }
    for (int idx = t; idx < NT * NT; idx += NTHR) ri[idx] = rel_idx[idx];

    const int oq = t & 15;    // output column sub-lane within 64-tile
    const int rg = t >> 4;    // row group 0..15: rows rg + 16*i

    int roff[4];
    #pragma unroll
    for (int i = 0; i < 4; ++i) {
        int r = rg + 16 * i;
        roff[i] = (r < NT ? r : NT - 1) * STR;   // clamp (stores are guarded)
    }

    // ==================== QKV projection ====================
    for (int tile = 0; tile < 9; ++tile) {
        __syncthreads();  // protect wt from previous tile's readers
        // fill wt o-major (float4 over k)
        for (int idx = t; idx < 64 * 48; idx += NTHR) {
            int o = idx / 48, k4 = idx - o * 48;
            *(float4*)&wt[o * STR + k4 * 4] =
                *(const float4*)&qkv_w[(tile * 64 + o) * DIMC + k4 * 4];
        }
        __syncthreads();

        float acc[4][4];
        #pragma unroll
        for (int i = 0; i < 4; ++i)
            #pragma unroll
            for (int w = 0; w < 4; ++w) acc[i][w] = 0.f;

        for (int kk = 0; kk < DIMC; kk += 4) {
            float4 wv[4];
            #pragma unroll
            for (int w = 0; w < 4; ++w)
                wv[w] = *(const float4*)&wt[(oq + 16 * w) * STR + kk];
            #pragma unroll
            for (int i = 0; i < 4; ++i) {
                float4 xv = *(const float4*)&xs[roff[i] + kk];
                #pragma unroll
                for (int w = 0; w < 4; ++w) acc[i][w] = dot4(xv, wv[w], acc[i][w]);
            }
        }

        int s = tile / 3;
        int cbase = (tile - s * 3) * 64;
        float* dst = (s == 0) ? qs : (s == 1 ? ks : vs);
        #pragma unroll
        for (int i = 0; i < 4; ++i) {
            int r = rg + 16 * i;
            if (r < NT) {
                #pragma unroll
                for (int w = 0; w < 4; ++w) {
                    int c  = cbase + oq + 16 * w;
                    int og = tile * 64 + oq + 16 * w;
                    dst[r * STR + c] = acc[i][w] + qkv_b[og];
                }
            }
        }
    }

    // ==================== attention per head ====================
    const float scale = 0.17677669529663687f;  // 32^-0.5
    const float* mrow = mask + (size_t)(b & (NWIN - 1)) * NT * NT;
    const int warp = t >> 5, lane = t & 31;
    const int ti = t >> 4, tj = t & 15;     // 16x16 logit thread grid
    const int av_i = t >> 2, av_d8 = t & 3; // AV: 64 rows x 4 d-groups

    for (int h = 0; h < NHEAD; ++h) {
        __syncthreads();  // qkv ready (h=0) / prev AV done reading lg (h>0)

        // ---- logits = scale*q.k + bias + mask (4x4 register tile, float4) ----
        {
            int ioff[4], joff[4];
            #pragma unroll
            for (int a = 0; a < 4; ++a) {
                int ia = ti + 16 * a;
                ioff[a] = (ia < NT ? ia : NT - 1) * STR + h * HD;
                int jb = tj + 16 * a;
                joff[a] = (jb < NT ? jb : NT - 1) * STR + h * HD;
            }
            float acc[4][4];
            #pragma unroll
            for (int a = 0; a < 4; ++a)
                #pragma unroll
                for (int c = 0; c < 4; ++c) acc[a][c] = 0.f;

            #pragma unroll
            for (int d = 0; d < HD; d += 4) {
                float4 q4[4], k4[4];
                #pragma unroll
                for (int a = 0; a < 4; ++a) q4[a] = *(const float4*)&qs[ioff[a] + d];
                #pragma unroll
                for (int c = 0; c < 4; ++c) k4[c] = *(const float4*)&ks[joff[c] + d];
                #pragma unroll
                for (int a = 0; a < 4; ++a)
                    #pragma unroll
                    for (int c = 0; c < 4; ++c) acc[a][c] = dot4(q4[a], k4[c], acc[a][c]);
            }

            #pragma unroll
            for (int a = 0; a < 4; ++a) {
                int i = ti + 16 * a;
                if (i < NT) {
                    #pragma unroll
                    for (int c = 0; c < 4; ++c) {
                        int j = tj + 16 * c;
                        if (j < NT) {
                            int idx = i * NT + j;
                            lg[idx] = acc[a][c] * scale
                                    + rpb[ri[idx] * NHEAD + h] + mrow[idx];
                        }
                    }
                }
            }
        }
        __syncthreads();

        // ---- softmax: one warp per row ----
        for (int i = warp; i < NT; i += 8) {
            float l1 = lg[i * NT + lane];
            bool  v2 = (lane + 32) < NT;
            float l2 = v2 ? lg[i * NT + lane + 32] : -1e30f;
            float m = fmaxf(l1, l2);
            #pragma unroll
            for (int o = 16; o; o >>= 1) m = fmaxf(m, __shfl_xor_sync(0xffffffffu, m, o));
            float e1 = __expf(l1 - m);
            float e2 = v2 ? __expf(l2 - m) : 0.f;
            float s2 = e1 + e2;
            #pragma unroll
            for (int o = 16; o; o >>= 1) s2 += __shfl_xor_sync(0xffffffffu, s2, o);
            float inv = 1.f / s2;
            float p1 = e1 * inv, p2 = e2 * inv;
            lg[i * NT + lane] = p1;
            if (v2) lg[i * NT + lane + 32] = p2;
            float* arow = attn_out + (((size_t)b * NHEAD + h) * NT + i) * NT;
            arow[lane] = p1;
            if (v2) arow[lane + 32] = p2;
        }
        __syncthreads();

        // ---- ctx[:, h*32+d] = attn @ v (float4 v loads, broadcast p) ----
        {
            int ii = (av_i < NT ? av_i : NT - 1);
            const float* pr = lg + ii * NT;
            const float* vb = vs + h * HD + av_d8 * 8;
            float4 a0 = make_float4(0.f, 0.f, 0.f, 0.f);
            float4 a1 = make_float4(0.f, 0.f, 0.f, 0.f);
            #pragma unroll 7
            for (int j = 0; j < NT; ++j) {
                float  p  = pr[j];
                float4 va = *(const float4*)&vb[j * STR];
                float4 vc = *(const float4*)&vb[j * STR + 4];
                a0.x = fmaf(p, va.x, a0.x); a0.y = fmaf(p, va.y, a0.y);
                a0.z = fmaf(p, va.z, a0.z); a0.w = fmaf(p, va.w, a0.w);
                a1.x = fmaf(p, vc.x, a1.x); a1.y = fmaf(p, vc.y, a1.y);
                a1.z = fmaf(p, vc.z, a1.z); a1.w = fmaf(p, vc.w, a1.w);
            }
            if (av_i < NT) {
                *(float4*)&xs[av_i * STR + h * HD + av_d8 * 8]     = a0;
                *(float4*)&xs[av_i * STR + h * HD + av_d8 * 8 + 4] = a1;
            }
        }
    }

    // ==================== output projection ====================
    for (int tile = 0; tile < 3; ++tile) {
        __syncthreads();  // AV done (tile 0) / prev tile's readers done
        for (int idx = t; idx < 64 * 48; idx += NTHR) {
            int o = idx / 48, k4 = idx - o * 48;
            *(float4*)&wt[o * STR + k4 * 4] =
                *(const float4*)&proj_w[(tile * 64 + o) * DIMC + k4 * 4];
        }
        __syncthreads();

        float acc[4][4];
        #pragma unroll
        for (int i = 0; i < 4; ++i)
            #pragma unroll
            for (int w = 0; w < 4; ++w) acc[i][w] = 0.f;

        for (int kk = 0; kk < DIMC; kk += 4) {
            float4 wv[4];
            #pragma unroll
            for (int w = 0; w < 4; ++w)
                wv[w] = *(const float4*)&wt[(oq + 16 * w) * STR + kk];
            #pragma unroll
            for (int i = 0; i < 4; ++i) {
                float4 xv = *(const float4*)&xs[roff[i] + kk];
                #pragma unroll
                for (int w = 0; w < 4; ++w) acc[i][w] = dot4(xv, wv[w], acc[i][w]);
            }
        }

        #pragma unroll
        for (int i = 0; i < 4; ++i) {
            int r = rg + 16 * i;
            if (r < NT) {
                #pragma unroll
                for (int w = 0; w < 4; ++w) {
                    int c = tile * 64 + oq + 16 * w;
                    out[((size_t)b * NT + r) * DIMC + c] = acc[i][w] + proj_b[c];
                }
            }
        }
    }
}

extern "C" void kernel_launch(void* const* d_in, const int* in_sizes, int n_in,
                              void* d_out, int out_size)
{
    const float* x      = (const float*)d_in[0];
    const float* mask   = (const float*)d_in[1];
    const float* qkv_w  = (const float*)d_in[2];
    const float* qkv_b  = (const float*)d_in[3];
    const float* proj_w = (const float*)d_in[4];
    const float* proj_b = (const float*)d_in[5];
    const float* rpb    = (const float*)d_in[6];
    const int*   relidx = (const int*)  d_in[7];

    float* out      = (float*)d_out;                         // [4096,49,192]
    float* attn_out = out + (size_t)BWIN * NT * DIMC;        // [4096,6,49,49]

    cudaFuncSetAttribute(win_attn_fused,
                         cudaFuncAttributeMaxDynamicSharedMemorySize, SMEM_BYTES);

    win_attn_fused<<<BWIN, NTHR, SMEM_BYTES>>>(
        x, mask, qkv_w, qkv_b, proj_w, proj_b, rpb, relidx, out, attn_out);
}